// round 2
// baseline (speedup 1.0000x reference)
#include <cuda_runtime.h>
#include <math.h>

#define FULL 0xffffffffu

static __device__ __forceinline__ float softplusf(float x) {
    return fmaxf(x, 0.f) + log1pf(expf(-fabsf(x)));
}
static __device__ __forceinline__ float sigmf(float x) {
    return 1.f / (1.f + expf(-x));
}
__host__ __device__ constexpr int TRI(int r, int c) { return r * (r + 1) / 2 + c; }

// =====================================================================
// Kernel 1: mass matrix + Coriolis contribution
//   out[b,i] = (M ddq)_i + Sum_j dq_j (dL_j u + L w_j)_i - w_i . u
// warp-per-element; 8 vectors (h + 7 tangents) pushed through the MLP.
// =====================================================================
__global__ __launch_bounds__(256, 2) void k_mass(
    const float* __restrict__ q, const float* __restrict__ dq, const float* __restrict__ ddq,
    const float* __restrict__ mW1, const float* __restrict__ mb1,
    const float* __restrict__ mW2, const float* __restrict__ mb2,
    const float* __restrict__ mW3, const float* __restrict__ mb3,
    float* __restrict__ out, int batch)
{
    extern __shared__ float sm[];
    float* sW1 = sm;                 // 7*128
    float* sb1 = sW1 + 7 * 128;      // 128
    float* sW2 = sb1 + 128;          // 128*128
    float* sb2 = sW2 + 128 * 128;    // 128
    float* sW3 = sb2 + 128;          // 128*28
    float* sb3 = sW3 + 128 * 28;     // 32 (padded)
    float* sScr = sb3 + 32;          // 8 warps * 224

    const int tid = threadIdx.x;
    for (int i = tid; i < 7 * 128; i += 256) sW1[i] = mW1[i];
    for (int i = tid; i < 128; i += 256) { sb1[i] = mb1[i]; sb2[i] = mb2[i]; }
    for (int i = tid; i < 128 * 128; i += 256) sW2[i] = mW2[i];
    for (int i = tid; i < 128 * 28; i += 256) sW3[i] = mW3[i];
    for (int i = tid; i < 28; i += 256) sb3[i] = mb3[i];
    __syncthreads();

    const int lane = tid & 31;
    const int warp = tid >> 5;
    float* scr = sScr + warp * 224;
    const int gw = blockIdx.x * 8 + warp;
    const int nw = gridDim.x * 8;

    for (int b = gw; b < batch; b += nw) {
        float qv = 0.f, dqv = 0.f, ddqv = 0.f;
        if (lane < 7) { qv = q[b * 7 + lane]; dqv = dq[b * 7 + lane]; ddqv = ddq[b * 7 + lane]; }

        // ---------------- layer 1 + tangents ----------------
        // x[0] = h1, x[1+j] = dh1 for direction j
        float x[8][4];
#pragma unroll
        for (int c = 0; c < 4; c++) {
            const int i = c * 32 + lane;
            float p = sb1[i];
#pragma unroll
            for (int d = 0; d < 7; d++) p += __shfl_sync(FULL, qv, d) * sW1[d * 128 + i];
            const float h = tanhf(p);
            const float g = 1.f - h * h;
            x[0][c] = h;
#pragma unroll
            for (int j = 0; j < 7; j++) x[1 + j][c] = g * sW1[j * 128 + i];
        }

        // ---------------- layer 2 (dominant GEMM) ----------------
        float acc[8][4];
#pragma unroll
        for (int r = 0; r < 4; r++) {
            acc[0][r] = sb2[r * 32 + lane];
#pragma unroll
            for (int v = 1; v < 8; v++) acc[v][r] = 0.f;
        }
#pragma unroll
        for (int cs = 0; cs < 4; cs++) {
#pragma unroll 4
            for (int l = 0; l < 32; l++) {
                const int i = cs * 32 + l;
                float xv[8];
#pragma unroll
                for (int v = 0; v < 8; v++) xv[v] = __shfl_sync(FULL, x[v][cs], l);
                const float* wr = sW2 + i * 128 + lane;
#pragma unroll
                for (int r = 0; r < 4; r++) {
                    const float w = wr[r * 32];
#pragma unroll
                    for (int v = 0; v < 8; v++) acc[v][r] += xv[v] * w;
                }
            }
        }
#pragma unroll
        for (int c = 0; c < 4; c++) {
            const float h = tanhf(acc[0][c]);
            const float g = 1.f - h * h;
            x[0][c] = h;
#pragma unroll
            for (int v = 1; v < 8; v++) x[v][c] = g * acc[v][c];
        }

        // ---------------- layer 3 ----------------
        float a3[8];
        a3[0] = (lane < 28) ? sb3[lane] : 0.f;
#pragma unroll
        for (int v = 1; v < 8; v++) a3[v] = 0.f;
#pragma unroll
        for (int cs = 0; cs < 4; cs++) {
#pragma unroll 4
            for (int l = 0; l < 32; l++) {
                const int i = cs * 32 + l;
                float xv[8];
#pragma unroll
                for (int v = 0; v < 8; v++) xv[v] = __shfl_sync(FULL, x[v][cs], l);
                float w = 0.f;
                if (lane < 28) w = sW3[i * 28 + lane];
#pragma unroll
                for (int v = 0; v < 8; v++) a3[v] += xv[v] * w;
            }
        }
        if (lane < 28) {
#pragma unroll
            for (int v = 0; v < 8; v++) scr[v * 28 + lane] = a3[v];
        }
        __syncwarp();

        // ---------------- Cholesky assembly (O(D^2)) ----------------
        float Lm[28];
#pragma unroll
        for (int t = 0; t < 28; t++) Lm[t] = scr[t];
        float sig[7];
#pragma unroll
        for (int r = 0; r < 7; r++) {
            const int td = TRI(r, r);
            const float p = Lm[td];
            sig[r] = sigmf(p);
            Lm[td] = softplusf(p);
        }
        // lane j (<7) holds dL_j; lanes >= 7 read valid-but-unused data (row 1)
        float dLm[28];
        {
            const int base = (lane < 7) ? (1 + lane) * 28 : 28;
#pragma unroll
            for (int t = 0; t < 28; t++) dLm[t] = scr[base + t];
#pragma unroll
            for (int r = 0; r < 7; r++) dLm[TRI(r, r)] *= sig[r];
        }
        float dqs[7];
#pragma unroll
        for (int r = 0; r < 7; r++) dqs[r] = __shfl_sync(FULL, dqv, r);

        // u = L^T dq, t2 = L^T ddq
        float u[7], t2[7];
#pragma unroll
        for (int c = 0; c < 7; c++) {
            float s = 0.f, s2 = 0.f;
#pragma unroll
            for (int r = 0; r < 7; r++) {
                if (r >= c) {
                    const float lv = Lm[TRI(r, c)];
                    s += lv * dqs[r];
                    s2 += lv * __shfl_sync(FULL, ddqv, r);
                }
            }
            u[c] = s; t2[c] = s2;
        }
        // a = dL_j u ; w = dL_j^T dq  (per lane j)
        float a[7], w[7];
#pragma unroll
        for (int r = 0; r < 7; r++) {
            float s = 0.f;
#pragma unroll
            for (int c = 0; c < 7; c++) if (c <= r) s += dLm[TRI(r, c)] * u[c];
            a[r] = s;
        }
#pragma unroll
        for (int c = 0; c < 7; c++) {
            float s = 0.f;
#pragma unroll
            for (int r = 0; r < 7; r++) if (r >= c) s += dLm[TRI(r, c)] * dqs[r];
            w[c] = s;
        }
        float wu = 0.f;
#pragma unroll
        for (int c = 0; c < 7; c++) wu += w[c] * u[c];

        const float dqj = (lane < 7) ? dqv : 0.f;
        // s1_i = Sum_j dq_j a_j[i]  (butterfly reduce, select at lane i)
        float s1_sel = 0.f;
#pragma unroll
        for (int i = 0; i < 7; i++) {
            float red = dqj * a[i];
#pragma unroll
            for (int off = 16; off > 0; off >>= 1) red += __shfl_xor_sync(FULL, red, off);
            if (lane == i) s1_sel = red;
        }
        // Wred_c = Sum_j dq_j w_j[c]  (all lanes keep it)
        float Wred[7];
#pragma unroll
        for (int c = 0; c < 7; c++) {
            float red = dqj * w[c];
#pragma unroll
            for (int off = 16; off > 0; off >>= 1) red += __shfl_xor_sync(FULL, red, off);
            Wred[c] = red;
        }
        // (L Wred)_i + (L t2)_i, selected per lane i
        float outsel = 0.f;
#pragma unroll
        for (int i = 0; i < 7; i++) {
            float s = 0.f;
#pragma unroll
            for (int c = 0; c <= i; c++) {
                const float lv = Lm[TRI(i, c)];
                s += lv * (Wred[c] + t2[c]);
            }
            if (lane == i) outsel = s;
        }
        if (lane < 7) out[b * 7 + lane] = outsel + s1_sel - wu;
        __syncwarp();
    }
}

// =====================================================================
// Kernel 2: damping + potential gradient, accumulated into out
//   out[b,i] += (L_d (L_d^T dq))_i + gradV_i
// =====================================================================
__global__ __launch_bounds__(256, 2) void k_damp(
    const float* __restrict__ q, const float* __restrict__ dq,
    const float* __restrict__ dW1, const float* __restrict__ db1,
    const float* __restrict__ dW2, const float* __restrict__ db2,
    const float* __restrict__ dW3, const float* __restrict__ db3,
    const float* __restrict__ pW1, const float* __restrict__ pb1,
    const float* __restrict__ pw2,
    float* __restrict__ out, int batch)
{
    extern __shared__ float sm[];
    float* sW1 = sm;                  // 14*128
    float* sb1 = sW1 + 14 * 128;      // 128
    float* sW2 = sb1 + 128;           // 128*128
    float* sb2 = sW2 + 128 * 128;     // 128
    float* sW3 = sb2 + 128;           // 128*28
    float* sb3 = sW3 + 128 * 28;      // 32
    float* spW1 = sb3 + 32;           // 7*128
    float* spb1 = spW1 + 7 * 128;     // 128
    float* sp2 = spb1 + 128;          // 128  (softplus(pw2))
    float* sScr = sp2 + 128;          // 8 warps * 28

    const int tid = threadIdx.x;
    for (int i = tid; i < 14 * 128; i += 256) sW1[i] = dW1[i];
    for (int i = tid; i < 128; i += 256) {
        sb1[i] = db1[i]; sb2[i] = db2[i];
        spb1[i] = pb1[i]; sp2[i] = softplusf(pw2[i]);
    }
    for (int i = tid; i < 128 * 128; i += 256) sW2[i] = dW2[i];
    for (int i = tid; i < 128 * 28; i += 256) sW3[i] = dW3[i];
    for (int i = tid; i < 28; i += 256) sb3[i] = db3[i];
    for (int i = tid; i < 7 * 128; i += 256) spW1[i] = pW1[i];
    __syncthreads();

    const int lane = tid & 31;
    const int warp = tid >> 5;
    float* scr = sScr + warp * 28;
    const int gw = blockIdx.x * 8 + warp;
    const int nw = gridDim.x * 8;

    for (int b = gw; b < batch; b += nw) {
        float xv = 0.f;  // lanes 0..6: q, lanes 7..13: dq
        if (lane < 7) xv = q[b * 7 + lane];
        else if (lane < 14) xv = dq[b * 7 + lane - 7];

        // layer 1
        float h1[4];
#pragma unroll
        for (int c = 0; c < 4; c++) {
            const int i = c * 32 + lane;
            float p = sb1[i];
#pragma unroll
            for (int d = 0; d < 14; d++) p += __shfl_sync(FULL, xv, d) * sW1[d * 128 + i];
            h1[c] = tanhf(p);
        }
        // layer 2
        float acc[4];
#pragma unroll
        for (int r = 0; r < 4; r++) acc[r] = sb2[r * 32 + lane];
#pragma unroll
        for (int cs = 0; cs < 4; cs++) {
#pragma unroll 4
            for (int l = 0; l < 32; l++) {
                const int i = cs * 32 + l;
                const float xb = __shfl_sync(FULL, h1[cs], l);
                const float* wr = sW2 + i * 128 + lane;
#pragma unroll
                for (int r = 0; r < 4; r++) acc[r] += xb * wr[r * 32];
            }
        }
#pragma unroll
        for (int c = 0; c < 4; c++) h1[c] = tanhf(acc[c]);
        // layer 3
        float a3 = (lane < 28) ? sb3[lane] : 0.f;
#pragma unroll
        for (int cs = 0; cs < 4; cs++) {
#pragma unroll 4
            for (int l = 0; l < 32; l++) {
                const int i = cs * 32 + l;
                const float xb = __shfl_sync(FULL, h1[cs], l);
                float w = 0.f;
                if (lane < 28) w = sW3[i * 28 + lane];
                a3 += xb * w;
            }
        }
        if (lane < 28) scr[lane] = a3;
        __syncwarp();

        // gradV: gv_j = Sum_h pW1[j,h] * sigmoid(z_h) * softplus(pw2_h)
        float gp[7];
#pragma unroll
        for (int j = 0; j < 7; j++) gp[j] = 0.f;
#pragma unroll
        for (int c = 0; c < 4; c++) {
            const int i = c * 32 + lane;
            float z = spb1[i];
#pragma unroll
            for (int d = 0; d < 7; d++) z += __shfl_sync(FULL, xv, d) * spW1[d * 128 + i];
            const float s = sigmf(z) * sp2[i];
#pragma unroll
            for (int j = 0; j < 7; j++) gp[j] += spW1[j * 128 + i] * s;
        }
        float gv[7];
#pragma unroll
        for (int j = 0; j < 7; j++) {
            float red = gp[j];
#pragma unroll
            for (int off = 16; off > 0; off >>= 1) red += __shfl_xor_sync(FULL, red, off);
            gv[j] = red;
        }

        // assembly: L_d, u = L^T dq, tau = L u
        float Lm[28];
#pragma unroll
        for (int t = 0; t < 28; t++) Lm[t] = scr[t];
#pragma unroll
        for (int r = 0; r < 7; r++) Lm[TRI(r, r)] = softplusf(Lm[TRI(r, r)]);
        float u[7];
#pragma unroll
        for (int c = 0; c < 7; c++) {
            float s = 0.f;
#pragma unroll
            for (int r = 0; r < 7; r++)
                if (r >= c) s += Lm[TRI(r, c)] * __shfl_sync(FULL, xv, 7 + r);
            u[c] = s;
        }
        float tsel = 0.f;
#pragma unroll
        for (int i = 0; i < 7; i++) {
            float s = 0.f;
#pragma unroll
            for (int c = 0; c <= i; c++) s += Lm[TRI(i, c)] * u[c];
            if (lane == i) tsel = s + gv[i];
        }
        if (lane < 7) {
            const int o = b * 7 + lane;
            out[o] = out[o] + tsel;
        }
        __syncwarp();
    }
}

// =====================================================================
extern "C" void kernel_launch(void* const* d_in, const int* in_sizes, int n_in,
                              void* d_out, int out_size)
{
    const float* q   = (const float*)d_in[0];
    const float* dq  = (const float*)d_in[1];
    const float* ddq = (const float*)d_in[2];
    const float* mW1 = (const float*)d_in[3];
    const float* mb1 = (const float*)d_in[4];
    const float* mW2 = (const float*)d_in[5];
    const float* mb2 = (const float*)d_in[6];
    const float* mW3 = (const float*)d_in[7];
    const float* mb3 = (const float*)d_in[8];
    const float* dW1 = (const float*)d_in[9];
    const float* db1 = (const float*)d_in[10];
    const float* dW2 = (const float*)d_in[11];
    const float* db2 = (const float*)d_in[12];
    const float* dW3 = (const float*)d_in[13];
    const float* db3 = (const float*)d_in[14];
    const float* pW1 = (const float*)d_in[15];
    const float* pb1 = (const float*)d_in[16];
    const float* pw2 = (const float*)d_in[17];
    float* out = (float*)d_out;

    const int batch = in_sizes[0] / 7;

    const size_t sm1 = (size_t)(7*128 + 128 + 128*128 + 128 + 128*28 + 32 + 8*224) * sizeof(float);
    const size_t sm2 = (size_t)(14*128 + 128 + 128*128 + 128 + 128*28 + 32 + 7*128 + 128 + 128 + 8*28) * sizeof(float);

    cudaFuncSetAttribute(k_mass, cudaFuncAttributeMaxDynamicSharedMemorySize, (int)sm1);
    cudaFuncSetAttribute(k_damp, cudaFuncAttributeMaxDynamicSharedMemorySize, (int)sm2);

    k_mass<<<296, 256, sm1>>>(q, dq, ddq, mW1, mb1, mW2, mb2, mW3, mb3, out, batch);
    k_damp<<<296, 256, sm2>>>(q, dq, dW1, db1, dW2, db2, dW3, db3, pW1, pb1, pw2, out, batch);
}

// round 3
// speedup vs baseline: 1.0009x; 1.0009x over previous
#include <cuda_runtime.h>
#include <math.h>

#define FULL 0xffffffffu

static __device__ __forceinline__ float softplusf(float x) {
    return fmaxf(x, 0.f) + log1pf(expf(-fabsf(x)));
}
static __device__ __forceinline__ float sigmf(float x) {
    return 1.f / (1.f + expf(-x));
}
__host__ __device__ constexpr int TRI(int r, int c) { return r * (r + 1) / 2 + c; }

// =====================================================================
// Kernel 1: mass matrix + Coriolis contribution
//   out[b,i] = (M ddq)_i + Sum_j dq_j (dL_j u + L w_j)_i - w_i . u
// warp-per-element; 8 vectors (h + 7 tangents) pushed through the MLP.
// =====================================================================
__global__ __launch_bounds__(256, 2) void k_mass(
    const float* __restrict__ q, const float* __restrict__ dq, const float* __restrict__ ddq,
    const float* __restrict__ mW1, const float* __restrict__ mb1,
    const float* __restrict__ mW2, const float* __restrict__ mb2,
    const float* __restrict__ mW3, const float* __restrict__ mb3,
    float* __restrict__ out, int batch)
{
    extern __shared__ float sm[];
    float* sW1 = sm;                 // 7*128
    float* sb1 = sW1 + 7 * 128;      // 128
    float* sW2 = sb1 + 128;          // 128*128
    float* sb2 = sW2 + 128 * 128;    // 128
    float* sW3 = sb2 + 128;          // 128*28
    float* sb3 = sW3 + 128 * 28;     // 32 (padded)
    float* sScr = sb3 + 32;          // 8 warps * 224

    const int tid = threadIdx.x;
    for (int i = tid; i < 7 * 128; i += 256) sW1[i] = mW1[i];
    for (int i = tid; i < 128; i += 256) { sb1[i] = mb1[i]; sb2[i] = mb2[i]; }
    for (int i = tid; i < 128 * 128; i += 256) sW2[i] = mW2[i];
    for (int i = tid; i < 128 * 28; i += 256) sW3[i] = mW3[i];
    for (int i = tid; i < 28; i += 256) sb3[i] = mb3[i];
    __syncthreads();

    const int lane = tid & 31;
    const int warp = tid >> 5;
    float* scr = sScr + warp * 224;
    const int gw = blockIdx.x * 8 + warp;
    const int nw = gridDim.x * 8;

    for (int b = gw; b < batch; b += nw) {
        float qv = 0.f, dqv = 0.f, ddqv = 0.f;
        if (lane < 7) { qv = q[b * 7 + lane]; dqv = dq[b * 7 + lane]; ddqv = ddq[b * 7 + lane]; }

        // ---------------- layer 1 + tangents ----------------
        // x[0] = h1, x[1+j] = dh1 for direction j
        float x[8][4];
#pragma unroll
        for (int c = 0; c < 4; c++) {
            const int i = c * 32 + lane;
            float p = sb1[i];
#pragma unroll
            for (int d = 0; d < 7; d++) p += __shfl_sync(FULL, qv, d) * sW1[d * 128 + i];
            const float h = tanhf(p);
            const float g = 1.f - h * h;
            x[0][c] = h;
#pragma unroll
            for (int j = 0; j < 7; j++) x[1 + j][c] = g * sW1[j * 128 + i];
        }

        // ---------------- layer 2 (dominant GEMM) ----------------
        float acc[8][4];
#pragma unroll
        for (int r = 0; r < 4; r++) {
            acc[0][r] = sb2[r * 32 + lane];
#pragma unroll
            for (int v = 1; v < 8; v++) acc[v][r] = 0.f;
        }
#pragma unroll
        for (int cs = 0; cs < 4; cs++) {
#pragma unroll 4
            for (int l = 0; l < 32; l++) {
                const int i = cs * 32 + l;
                float xv[8];
#pragma unroll
                for (int v = 0; v < 8; v++) xv[v] = __shfl_sync(FULL, x[v][cs], l);
                const float* wr = sW2 + i * 128 + lane;
#pragma unroll
                for (int r = 0; r < 4; r++) {
                    const float w = wr[r * 32];
#pragma unroll
                    for (int v = 0; v < 8; v++) acc[v][r] += xv[v] * w;
                }
            }
        }
#pragma unroll
        for (int c = 0; c < 4; c++) {
            const float h = tanhf(acc[0][c]);
            const float g = 1.f - h * h;
            x[0][c] = h;
#pragma unroll
            for (int v = 1; v < 8; v++) x[v][c] = g * acc[v][c];
        }

        // ---------------- layer 3 ----------------
        float a3[8];
        a3[0] = (lane < 28) ? sb3[lane] : 0.f;
#pragma unroll
        for (int v = 1; v < 8; v++) a3[v] = 0.f;
#pragma unroll
        for (int cs = 0; cs < 4; cs++) {
#pragma unroll 4
            for (int l = 0; l < 32; l++) {
                const int i = cs * 32 + l;
                float xv[8];
#pragma unroll
                for (int v = 0; v < 8; v++) xv[v] = __shfl_sync(FULL, x[v][cs], l);
                float w = 0.f;
                if (lane < 28) w = sW3[i * 28 + lane];
#pragma unroll
                for (int v = 0; v < 8; v++) a3[v] += xv[v] * w;
            }
        }
        if (lane < 28) {
#pragma unroll
            for (int v = 0; v < 8; v++) scr[v * 28 + lane] = a3[v];
        }
        __syncwarp();

        // ---------------- Cholesky assembly (O(D^2)) ----------------
        float Lm[28];
#pragma unroll
        for (int t = 0; t < 28; t++) Lm[t] = scr[t];
        float sig[7];
#pragma unroll
        for (int r = 0; r < 7; r++) {
            const int td = TRI(r, r);
            const float p = Lm[td];
            sig[r] = sigmf(p);
            Lm[td] = softplusf(p);
        }
        // lane j (<7) holds dL_j; lanes >= 7 read valid-but-unused data (row 1)
        float dLm[28];
        {
            const int base = (lane < 7) ? (1 + lane) * 28 : 28;
#pragma unroll
            for (int t = 0; t < 28; t++) dLm[t] = scr[base + t];
#pragma unroll
            for (int r = 0; r < 7; r++) dLm[TRI(r, r)] *= sig[r];
        }
        float dqs[7];
#pragma unroll
        for (int r = 0; r < 7; r++) dqs[r] = __shfl_sync(FULL, dqv, r);

        // u = L^T dq, t2 = L^T ddq
        float u[7], t2[7];
#pragma unroll
        for (int c = 0; c < 7; c++) {
            float s = 0.f, s2 = 0.f;
#pragma unroll
            for (int r = 0; r < 7; r++) {
                if (r >= c) {
                    const float lv = Lm[TRI(r, c)];
                    s += lv * dqs[r];
                    s2 += lv * __shfl_sync(FULL, ddqv, r);
                }
            }
            u[c] = s; t2[c] = s2;
        }
        // a = dL_j u ; w = dL_j^T dq  (per lane j)
        float a[7], w[7];
#pragma unroll
        for (int r = 0; r < 7; r++) {
            float s = 0.f;
#pragma unroll
            for (int c = 0; c < 7; c++) if (c <= r) s += dLm[TRI(r, c)] * u[c];
            a[r] = s;
        }
#pragma unroll
        for (int c = 0; c < 7; c++) {
            float s = 0.f;
#pragma unroll
            for (int r = 0; r < 7; r++) if (r >= c) s += dLm[TRI(r, c)] * dqs[r];
            w[c] = s;
        }
        float wu = 0.f;
#pragma unroll
        for (int c = 0; c < 7; c++) wu += w[c] * u[c];

        const float dqj = (lane < 7) ? dqv : 0.f;
        // s1_i = Sum_j dq_j a_j[i]  (butterfly reduce, select at lane i)
        float s1_sel = 0.f;
#pragma unroll
        for (int i = 0; i < 7; i++) {
            float red = dqj * a[i];
#pragma unroll
            for (int off = 16; off > 0; off >>= 1) red += __shfl_xor_sync(FULL, red, off);
            if (lane == i) s1_sel = red;
        }
        // Wred_c = Sum_j dq_j w_j[c]  (all lanes keep it)
        float Wred[7];
#pragma unroll
        for (int c = 0; c < 7; c++) {
            float red = dqj * w[c];
#pragma unroll
            for (int off = 16; off > 0; off >>= 1) red += __shfl_xor_sync(FULL, red, off);
            Wred[c] = red;
        }
        // (L Wred)_i + (L t2)_i, selected per lane i
        float outsel = 0.f;
#pragma unroll
        for (int i = 0; i < 7; i++) {
            float s = 0.f;
#pragma unroll
            for (int c = 0; c <= i; c++) {
                const float lv = Lm[TRI(i, c)];
                s += lv * (Wred[c] + t2[c]);
            }
            if (lane == i) outsel = s;
        }
        if (lane < 7) out[b * 7 + lane] = outsel + s1_sel - wu;
        __syncwarp();
    }
}

// =====================================================================
// Kernel 2: damping + potential gradient, accumulated into out
//   out[b,i] += (L_d (L_d^T dq))_i + gradV_i
// =====================================================================
__global__ __launch_bounds__(256, 2) void k_damp(
    const float* __restrict__ q, const float* __restrict__ dq,
    const float* __restrict__ dW1, const float* __restrict__ db1,
    const float* __restrict__ dW2, const float* __restrict__ db2,
    const float* __restrict__ dW3, const float* __restrict__ db3,
    const float* __restrict__ pW1, const float* __restrict__ pb1,
    const float* __restrict__ pw2,
    float* __restrict__ out, int batch)
{
    extern __shared__ float sm[];
    float* sW1 = sm;                  // 14*128
    float* sb1 = sW1 + 14 * 128;      // 128
    float* sW2 = sb1 + 128;           // 128*128
    float* sb2 = sW2 + 128 * 128;     // 128
    float* sW3 = sb2 + 128;           // 128*28
    float* sb3 = sW3 + 128 * 28;      // 32
    float* spW1 = sb3 + 32;           // 7*128
    float* spb1 = spW1 + 7 * 128;     // 128
    float* sp2 = spb1 + 128;          // 128  (softplus(pw2))
    float* sScr = sp2 + 128;          // 8 warps * 28

    const int tid = threadIdx.x;
    for (int i = tid; i < 14 * 128; i += 256) sW1[i] = dW1[i];
    for (int i = tid; i < 128; i += 256) {
        sb1[i] = db1[i]; sb2[i] = db2[i];
        spb1[i] = pb1[i]; sp2[i] = softplusf(pw2[i]);
    }
    for (int i = tid; i < 128 * 128; i += 256) sW2[i] = dW2[i];
    for (int i = tid; i < 128 * 28; i += 256) sW3[i] = dW3[i];
    for (int i = tid; i < 28; i += 256) sb3[i] = db3[i];
    for (int i = tid; i < 7 * 128; i += 256) spW1[i] = pW1[i];
    __syncthreads();

    const int lane = tid & 31;
    const int warp = tid >> 5;
    float* scr = sScr + warp * 28;
    const int gw = blockIdx.x * 8 + warp;
    const int nw = gridDim.x * 8;

    for (int b = gw; b < batch; b += nw) {
        float xv = 0.f;  // lanes 0..6: q, lanes 7..13: dq
        if (lane < 7) xv = q[b * 7 + lane];
        else if (lane < 14) xv = dq[b * 7 + lane - 7];

        // layer 1
        float h1[4];
#pragma unroll
        for (int c = 0; c < 4; c++) {
            const int i = c * 32 + lane;
            float p = sb1[i];
#pragma unroll
            for (int d = 0; d < 14; d++) p += __shfl_sync(FULL, xv, d) * sW1[d * 128 + i];
            h1[c] = tanhf(p);
        }
        // layer 2
        float acc[4];
#pragma unroll
        for (int r = 0; r < 4; r++) acc[r] = sb2[r * 32 + lane];
#pragma unroll
        for (int cs = 0; cs < 4; cs++) {
#pragma unroll 4
            for (int l = 0; l < 32; l++) {
                const int i = cs * 32 + l;
                const float xb = __shfl_sync(FULL, h1[cs], l);
                const float* wr = sW2 + i * 128 + lane;
#pragma unroll
                for (int r = 0; r < 4; r++) acc[r] += xb * wr[r * 32];
            }
        }
#pragma unroll
        for (int c = 0; c < 4; c++) h1[c] = tanhf(acc[c]);
        // layer 3
        float a3 = (lane < 28) ? sb3[lane] : 0.f;
#pragma unroll
        for (int cs = 0; cs < 4; cs++) {
#pragma unroll 4
            for (int l = 0; l < 32; l++) {
                const int i = cs * 32 + l;
                const float xb = __shfl_sync(FULL, h1[cs], l);
                float w = 0.f;
                if (lane < 28) w = sW3[i * 28 + lane];
                a3 += xb * w;
            }
        }
        if (lane < 28) scr[lane] = a3;
        __syncwarp();

        // gradV: gv_j = Sum_h pW1[j,h] * sigmoid(z_h) * softplus(pw2_h)
        float gp[7];
#pragma unroll
        for (int j = 0; j < 7; j++) gp[j] = 0.f;
#pragma unroll
        for (int c = 0; c < 4; c++) {
            const int i = c * 32 + lane;
            float z = spb1[i];
#pragma unroll
            for (int d = 0; d < 7; d++) z += __shfl_sync(FULL, xv, d) * spW1[d * 128 + i];
            const float s = sigmf(z) * sp2[i];
#pragma unroll
            for (int j = 0; j < 7; j++) gp[j] += spW1[j * 128 + i] * s;
        }
        float gv[7];
#pragma unroll
        for (int j = 0; j < 7; j++) {
            float red = gp[j];
#pragma unroll
            for (int off = 16; off > 0; off >>= 1) red += __shfl_xor_sync(FULL, red, off);
            gv[j] = red;
        }

        // assembly: L_d, u = L^T dq, tau = L u
        float Lm[28];
#pragma unroll
        for (int t = 0; t < 28; t++) Lm[t] = scr[t];
#pragma unroll
        for (int r = 0; r < 7; r++) Lm[TRI(r, r)] = softplusf(Lm[TRI(r, r)]);
        float u[7];
#pragma unroll
        for (int c = 0; c < 7; c++) {
            float s = 0.f;
#pragma unroll
            for (int r = 0; r < 7; r++)
                if (r >= c) s += Lm[TRI(r, c)] * __shfl_sync(FULL, xv, 7 + r);
            u[c] = s;
        }
        float tsel = 0.f;
#pragma unroll
        for (int i = 0; i < 7; i++) {
            float s = 0.f;
#pragma unroll
            for (int c = 0; c <= i; c++) s += Lm[TRI(i, c)] * u[c];
            if (lane == i) tsel = s + gv[i];
        }
        if (lane < 7) {
            const int o = b * 7 + lane;
            out[o] = out[o] + tsel;
        }
        __syncwarp();
    }
}

// =====================================================================
extern "C" void kernel_launch(void* const* d_in, const int* in_sizes, int n_in,
                              void* d_out, int out_size)
{
    const float* q   = (const float*)d_in[0];
    const float* dq  = (const float*)d_in[1];
    const float* ddq = (const float*)d_in[2];
    const float* mW1 = (const float*)d_in[3];
    const float* mb1 = (const float*)d_in[4];
    const float* mW2 = (const float*)d_in[5];
    const float* mb2 = (const float*)d_in[6];
    const float* mW3 = (const float*)d_in[7];
    const float* mb3 = (const float*)d_in[8];
    const float* dW1 = (const float*)d_in[9];
    const float* db1 = (const float*)d_in[10];
    const float* dW2 = (const float*)d_in[11];
    const float* db2 = (const float*)d_in[12];
    const float* dW3 = (const float*)d_in[13];
    const float* db3 = (const float*)d_in[14];
    const float* pW1 = (const float*)d_in[15];
    const float* pb1 = (const float*)d_in[16];
    const float* pw2 = (const float*)d_in[17];
    float* out = (float*)d_out;

    const int batch = in_sizes[0] / 7;

    const size_t sm1 = (size_t)(7*128 + 128 + 128*128 + 128 + 128*28 + 32 + 8*224) * sizeof(float);
    const size_t sm2 = (size_t)(14*128 + 128 + 128*128 + 128 + 128*28 + 32 + 7*128 + 128 + 128 + 8*28) * sizeof(float);

    cudaFuncSetAttribute(k_mass, cudaFuncAttributeMaxDynamicSharedMemorySize, (int)sm1);
    cudaFuncSetAttribute(k_damp, cudaFuncAttributeMaxDynamicSharedMemorySize, (int)sm2);

    k_mass<<<296, 256, sm1>>>(q, dq, ddq, mW1, mb1, mW2, mb2, mW3, mb3, out, batch);
    k_damp<<<296, 256, sm2>>>(q, dq, dW1, db1, dW2, db2, dW3, db3, pW1, pb1, pw2, out, batch);
}